// round 1
// baseline (speedup 1.0000x reference)
#include <cuda_runtime.h>
#include <cuda_bf16.h>

#define NS   4
#define NA   8192
#define NC   8
#define THR2 (1.1f * 1.1f)

#define TI 512                 // i-tile (2 atoms per thread, 256 threads)
#define TJ 512                 // j-tile
#define NTILE (NA / TI)        // 16

// Scratch (device globals: no allocation allowed in kernel_launch)
__device__ float4 g_packed[NS * NA];   // (x, y, z, |p|^2)
__device__ int    g_chain[NA];
__device__ int    g_counts[NS * NC * NC];  // ordered-pair (i<j) counts [s][ci][cj]
__device__ int    g_npc[NC];               // atoms per chain

// ---------------------------------------------------------------------------
__global__ void zero_kernel() {
    int t = threadIdx.x;
    if (t < NS * NC * NC) g_counts[t] = 0;
    if (t < NC)           g_npc[t] = 0;
}

// ---------------------------------------------------------------------------
__global__ void prep_kernel(const float* __restrict__ coord,
                            const int*   __restrict__ asym,
                            const int*   __restrict__ a2t) {
    int idx = blockIdx.x * blockDim.x + threadIdx.x;   // over NS*NA
    if (idx < NA) {
        int c = asym[a2t[idx]];
        g_chain[idx] = c;
        atomicAdd(&g_npc[c], 1);
    }
    if (idx < NS * NA) {
        float x = coord[3 * idx + 0];
        float y = coord[3 * idx + 1];
        float z = coord[3 * idx + 2];
        g_packed[idx] = make_float4(x, y, z, x * x + y * y + z * z);
    }
}

// ---------------------------------------------------------------------------
// Inner loop, templated on whether this is a diagonal tile (needs j > i).
template <bool DIAG>
__device__ __forceinline__ void pair_loop(
    const float4* __restrict__ sj, const int* __restrict__ scj,
    int* __restrict__ scnt,
    float4 p1, float r1, int c1,
    float4 p2, float r2, int c2,
    int tid)
{
#pragma unroll 8
    for (int jj = 0; jj < TJ; ++jj) {
        float4 pj = sj[jj];          // broadcast LDS.128 (warp-uniform jj)
        int    cj = scj[jj];
        float dot1 = fmaf(p1.x, pj.x, fmaf(p1.y, pj.y, p1.z * pj.z));
        float dot2 = fmaf(p2.x, pj.x, fmaf(p2.y, pj.y, p2.z * pj.z));
        // d2 < thr^2  <=>  qj - 2*dot < thr^2 - qi
        bool cl1 = (fmaf(-2.0f, dot1, pj.w) < r1) && (c1 != cj);
        bool cl2 = (fmaf(-2.0f, dot2, pj.w) < r2) && (c2 != cj);
        if (DIAG) {
            cl1 = cl1 && (jj > tid);
            cl2 = cl2 && (jj > tid + 256);
        }
        if (cl1) atomicAdd(&scnt[c1 * NC + cj], 1);  // rare (~1e-3 hit rate)
        if (cl2) atomicAdd(&scnt[c2 * NC + cj], 1);
    }
}

__global__ __launch_bounds__(256, 4) void pair_kernel() {
    int bi = blockIdx.x;           // i-tile
    int bj = blockIdx.y;           // j-tile
    if (bj < bi) return;           // upper triangle only
    int s  = blockIdx.z;
    int tid = threadIdx.x;

    __shared__ float4 sj[TJ];
    __shared__ int    scj[TJ];
    __shared__ int    scnt[NC * NC];

    const float4* pk = g_packed + s * NA;
    int jbase = bj * TJ;
    sj[tid]        = pk[jbase + tid];
    sj[tid + 256]  = pk[jbase + tid + 256];
    scj[tid]       = g_chain[jbase + tid];
    scj[tid + 256] = g_chain[jbase + tid + 256];
    if (tid < NC * NC) scnt[tid] = 0;
    __syncthreads();

    int i1 = bi * TI + tid;
    int i2 = i1 + 256;
    float4 p1 = pk[i1];
    float4 p2 = pk[i2];
    float  r1 = THR2 - p1.w;
    float  r2 = THR2 - p2.w;
    int    c1 = g_chain[i1];
    int    c2 = g_chain[i2];

    if (bi == bj)
        pair_loop<true >(sj, scj, scnt, p1, r1, c1, p2, r2, c2, tid);
    else
        pair_loop<false>(sj, scj, scnt, p1, r1, c1, p2, r2, c2, tid);

    __syncthreads();
    if (tid < NC * NC) {
        int v = scnt[tid];
        if (v) atomicAdd(&g_counts[s * NC * NC + tid], v);
    }
}

// ---------------------------------------------------------------------------
// Output layout: [ has_af3_clash (S*C*C floats) | details (S*C*C*2 floats) ]
__global__ void finalize_kernel(float* __restrict__ out) {
    int t = threadIdx.x;           // 0..255 -> (s, a, b)
    int s = t / (NC * NC);
    int r = t % (NC * NC);
    int a = r / NC;
    int b = r % NC;

    int tot_i = 0;
    if (a != b)
        tot_i = g_counts[s * NC * NC + a * NC + b] +
                g_counts[s * NC * NC + b * NC + a];
    float tot = (float)tot_i;
    float mn  = (float)min(g_npc[a], g_npc[b]);
    float rel = tot / mn;
    bool  has = (tot > 100.0f) || (rel > 0.5f);

    out[t]                       = has ? 1.0f : 0.0f;
    out[NS * NC * NC + 2 * t]    = tot;
    out[NS * NC * NC + 2 * t + 1] = rel;
}

// ---------------------------------------------------------------------------
extern "C" void kernel_launch(void* const* d_in, const int* in_sizes, int n_in,
                              void* d_out, int out_size) {
    const float* coord = (const float*)d_in[0];   // [S, N, 3] f32
    const int*   asym  = (const int*)  d_in[1];   // [N_TOKENS] i32
    const int*   a2t   = (const int*)  d_in[2];   // [N] i32
    float*       out   = (float*)d_out;

    zero_kernel<<<1, 256>>>();
    prep_kernel<<<(NS * NA + 255) / 256, 256>>>(coord, asym, a2t);
    dim3 grid(NTILE, NTILE, NS);
    pair_kernel<<<grid, 256>>>();
    finalize_kernel<<<1, 256>>>(out);
}

// round 2
// speedup vs baseline: 1.8744x; 1.8744x over previous
#include <cuda_runtime.h>
#include <cuda_bf16.h>

#define NS     4
#define NA     8192
#define NC     8
#define THR2   1.21f
#define TILE   512
#define NT     (NA / TILE)            // 16
#define NTP    (NT * (NT + 1) / 2)    // 136 tile-pairs
#define UNROLL 8

// Device-global scratch (no allocation allowed in kernel_launch)
__device__ float4 g_packed[NS * NA];        // (x, y, z, |p|^2)
__device__ int    g_chain[NA];
__device__ int    g_counts[NS * NC * NC];   // weighted ordered-bucket counts

// ---------------------------------------------------------------------------
// packed f32x2 helpers
__device__ __forceinline__ unsigned long long pack2(float lo, float hi) {
    unsigned long long r;
    asm("mov.b64 %0, {%1, %2};" : "=l"(r) : "f"(lo), "f"(hi));
    return r;
}
__device__ __forceinline__ unsigned long long fma2(unsigned long long a,
                                                   unsigned long long b,
                                                   unsigned long long c) {
    unsigned long long d;
    asm("fma.rn.f32x2 %0, %1, %2, %3;" : "=l"(d) : "l"(a), "l"(b), "l"(c));
    return d;
}
__device__ __forceinline__ unsigned long long add2(unsigned long long a,
                                                   unsigned long long b) {
    unsigned long long d;
    asm("add.rn.f32x2 %0, %1, %2;" : "=l"(d) : "l"(a), "l"(b));
    return d;
}
__device__ __forceinline__ void unpack2(unsigned long long v,
                                        unsigned int& lo, unsigned int& hi) {
    asm("mov.b64 {%0, %1}, %2;" : "=r"(lo), "=r"(hi) : "l"(v));
}

// ---------------------------------------------------------------------------
// prep: zero counters, pack coords, map atom -> chain
__global__ void prep_kernel(const float* __restrict__ coord,
                            const int*   __restrict__ asym,
                            const int*   __restrict__ a2t) {
    int idx = blockIdx.x * blockDim.x + threadIdx.x;   // over NS*NA
    if (blockIdx.x == 0 && threadIdx.x < NS * NC * NC)
        g_counts[threadIdx.x] = 0;
    if (idx < NA)
        g_chain[idx] = asym[a2t[idx]];
    if (idx < NS * NA) {
        float x = coord[3 * idx + 0];
        float y = coord[3 * idx + 1];
        float z = coord[3 * idx + 2];
        g_packed[idx] = make_float4(x, y, z, x * x + y * y + z * z);
    }
}

// ---------------------------------------------------------------------------
// pair kernel: 512x512 tiles over the upper triangle of tile space.
// Every tile runs the FULL 512x512 loop (no per-pair masking):
//   off-diag tile (bi<bj): each unordered cross pair counted once  -> weight 2
//   diag tile (bi==bj):    each unordered pair counted twice       -> weight 1
// finalize halves the sum. Self pairs / same-chain land in diagonal chain
// buckets which the reference masks anyway.
__global__ __launch_bounds__(256, 4) void pair_kernel() {
    __shared__ ulonglong2 sA[TILE / 2];   // (xx, yy) packed j-pairs
    __shared__ ulonglong2 sB[TILE / 2];   // (zz, ww) packed j-pairs
    __shared__ int        scj[TILE];
    __shared__ int        scnt[NC * NC];

    // decode triangular tile pair
    int t = blockIdx.x, bi = 0;
    while (t >= NT - bi) { t -= NT - bi; ++bi; }
    int bj = bi + t;
    int s  = blockIdx.y;
    int w  = (bi == bj) ? 1 : 2;
    int tid = threadIdx.x;

    const float4* pk = g_packed + s * NA;

    // fill j-tile smem: thread k packs atoms (2k, 2k+1)
    {
        int j0 = bj * TILE + 2 * tid;
        float4 a = pk[j0];
        float4 b = pk[j0 + 1];
        sA[tid] = make_ulonglong2(pack2(a.x, b.x), pack2(a.y, b.y));
        sB[tid] = make_ulonglong2(pack2(a.z, b.z), pack2(a.w, b.w));
        scj[2 * tid]     = g_chain[j0];
        scj[2 * tid + 1] = g_chain[j0 + 1];
    }
    if (tid < NC * NC) scnt[tid] = 0;

    // i-atoms: tid and tid+256, coords pre-scaled by -2, thr folded in
    int i1 = bi * TILE + tid;
    int i2 = i1 + 256;
    float4 p1 = pk[i1], p2 = pk[i2];
    unsigned long long ax1 = pack2(-2.0f * p1.x, -2.0f * p1.x);
    unsigned long long ay1 = pack2(-2.0f * p1.y, -2.0f * p1.y);
    unsigned long long az1 = pack2(-2.0f * p1.z, -2.0f * p1.z);
    unsigned long long k1  = pack2(p1.w - THR2, p1.w - THR2);
    unsigned long long ax2 = pack2(-2.0f * p2.x, -2.0f * p2.x);
    unsigned long long ay2 = pack2(-2.0f * p2.y, -2.0f * p2.y);
    unsigned long long az2 = pack2(-2.0f * p2.z, -2.0f * p2.z);
    unsigned long long k2  = pack2(p2.w - THR2, p2.w - THR2);
    int c1 = g_chain[i1] * NC;
    int c2 = g_chain[i2] * NC;

    __syncthreads();

    for (int jj0 = 0; jj0 < TILE / 2; jj0 += UNROLL) {
        unsigned int acc1 = 0, acc2 = 0;
#pragma unroll
        for (int q = 0; q < UNROLL; ++q) {
            ulonglong2 A = sA[jj0 + q];
            ulonglong2 B = sB[jj0 + q];
            // d = q_i + q_j - 2*dot - thr^2   (packed over 2 j-atoms)
            unsigned long long d1 =
                add2(fma2(az1, B.x, fma2(ay1, A.y, fma2(ax1, A.x, B.y))), k1);
            unsigned long long d2 =
                add2(fma2(az2, B.x, fma2(ay2, A.y, fma2(ax2, A.x, B.y))), k2);
            unsigned int l1, h1, l2, h2;
            unpack2(d1, l1, h1);
            unpack2(d2, l2, h2);
            acc1 |= l1 | h1;           // sign bit sticks if any clash
            acc2 |= l2 | h2;
        }
        if ((int)(acc1 | acc2) < 0) {
            // rare slow path: identical instruction sequence -> identical d
            for (int q = 0; q < UNROLL; ++q) {
                ulonglong2 A = sA[jj0 + q];
                ulonglong2 B = sB[jj0 + q];
                unsigned long long d1 =
                    add2(fma2(az1, B.x, fma2(ay1, A.y, fma2(ax1, A.x, B.y))), k1);
                unsigned long long d2 =
                    add2(fma2(az2, B.x, fma2(ay2, A.y, fma2(ax2, A.x, B.y))), k2);
                unsigned int l1, h1, l2, h2;
                unpack2(d1, l1, h1);
                unpack2(d2, l2, h2);
                int ja = 2 * (jj0 + q), jb = ja + 1;
                if ((int)l1 < 0) atomicAdd(&scnt[c1 + scj[ja]], w);
                if ((int)h1 < 0) atomicAdd(&scnt[c1 + scj[jb]], w);
                if ((int)l2 < 0) atomicAdd(&scnt[c2 + scj[ja]], w);
                if ((int)h2 < 0) atomicAdd(&scnt[c2 + scj[jb]], w);
            }
        }
    }

    __syncthreads();
    if (tid < NC * NC) {
        int v = scnt[tid];
        if (v) atomicAdd(&g_counts[s * NC * NC + tid], v);
    }
}

// ---------------------------------------------------------------------------
// finalize: per-chain atom histogram + thresholds + output
// layout: [ has (S*C*C floats) | details (S*C*C*2 floats, (total, rel)) ]
__global__ void finalize_kernel(float* __restrict__ out) {
    __shared__ int h[NC];
    int tid = threadIdx.x;
    if (tid < NC) h[tid] = 0;
    __syncthreads();
    for (int i = tid; i < NA; i += 256)
        atomicAdd(&h[g_chain[i]], 1);
    __syncthreads();

    int s = tid / (NC * NC);
    int r = tid % (NC * NC);
    int a = r / NC;
    int b = r % NC;

    int tot_i = 0;
    if (a != b)
        tot_i = (g_counts[s * NC * NC + a * NC + b] +
                 g_counts[s * NC * NC + b * NC + a]) >> 1;   // exact (even)
    float tot = (float)tot_i;
    float mn  = (float)min(h[a], h[b]);
    float rel = tot / mn;
    bool  has = (tot > 100.0f) || (rel > 0.5f);

    out[tid]                        = has ? 1.0f : 0.0f;
    out[NS * NC * NC + 2 * tid]     = tot;
    out[NS * NC * NC + 2 * tid + 1] = rel;
}

// ---------------------------------------------------------------------------
extern "C" void kernel_launch(void* const* d_in, const int* in_sizes, int n_in,
                              void* d_out, int out_size) {
    const float* coord = (const float*)d_in[0];   // [S, N, 3] f32
    const int*   asym  = (const int*)  d_in[1];   // [N_TOKENS] i32
    const int*   a2t   = (const int*)  d_in[2];   // [N] i32
    float*       out   = (float*)d_out;

    prep_kernel<<<(NS * NA + 255) / 256, 256>>>(coord, asym, a2t);
    dim3 grid(NTP, NS);
    pair_kernel<<<grid, 256>>>();
    finalize_kernel<<<1, 256>>>(out);
}

// round 3
// speedup vs baseline: 2.0912x; 1.1157x over previous
#include <cuda_runtime.h>
#include <cuda_bf16.h>

#define NS     4
#define NA     8192
#define NC     8
#define THR2   1.21f
#define TILE   512
#define NT     (NA / TILE)            // 16
#define NTP    (NT * (NT + 1) / 2)    // 136 tile-pairs
#define UNROLL 4

// Weighted ordered-bucket counts. Zero-initialized at module load; finalize
// re-zeroes it after consuming, so every graph replay sees zeros.
__device__ int g_counts[NS * NC * NC];

// ---------------------------------------------------------------------------
// packed f32x2 helpers
__device__ __forceinline__ unsigned long long pack2(float lo, float hi) {
    unsigned long long r;
    asm("mov.b64 %0, {%1, %2};" : "=l"(r) : "f"(lo), "f"(hi));
    return r;
}
__device__ __forceinline__ unsigned long long fma2(unsigned long long a,
                                                   unsigned long long b,
                                                   unsigned long long c) {
    unsigned long long d;
    asm("fma.rn.f32x2 %0, %1, %2, %3;" : "=l"(d) : "l"(a), "l"(b), "l"(c));
    return d;
}
__device__ __forceinline__ unsigned long long add2(unsigned long long a,
                                                   unsigned long long b) {
    unsigned long long d;
    asm("add.rn.f32x2 %0, %1, %2;" : "=l"(d) : "l"(a), "l"(b));
    return d;
}
__device__ __forceinline__ void unpack2(unsigned long long v,
                                        unsigned int& lo, unsigned int& hi) {
    asm("mov.b64 {%0, %1}, %2;" : "=r"(lo), "=r"(hi) : "l"(v));
}

#define SIGNS 0x8000000080000000ULL

// ---------------------------------------------------------------------------
// Fused pack + pair kernel. 512x512 tiles over the upper triangle of tile
// space; every tile runs the full loop (no per-pair masking):
//   off-diag tile (bi<bj): each unordered cross pair counted once  -> weight 2
//   diag tile (bi==bj):    each unordered pair counted twice       -> weight 1
// finalize halves the sum. Self/same-chain pairs land in diagonal chain
// buckets, which the reference masks anyway.
__global__ __launch_bounds__(256, 4) void pair_kernel(
    const float* __restrict__ coord,
    const int*   __restrict__ asym,
    const int*   __restrict__ a2t)
{
    __shared__ ulonglong2 sA[TILE / 2];   // (xx, yy) packed j-pairs
    __shared__ ulonglong2 sB[TILE / 2];   // (zz, cc) with cc = q_j - thr^2
    __shared__ int        scj[TILE];
    __shared__ int        scnt[NC * NC];

    // decode triangular tile pair
    int t = blockIdx.x, bi = 0;
    while (t >= NT - bi) { t -= NT - bi; ++bi; }
    int bj = bi + t;
    int s  = blockIdx.y;
    int w  = (bi == bj) ? 1 : 2;
    int tid = threadIdx.x;

    const float* C = coord + (size_t)s * NA * 3;

    // fill j-tile smem: thread packs atoms (2*tid, 2*tid+1) of tile bj
    {
        int j0 = bj * TILE + 2 * tid;
        float2 u0 = *(const float2*)(C + 3 * j0);       // xa ya
        float2 u1 = *(const float2*)(C + 3 * j0 + 2);   // za xb
        float2 u2 = *(const float2*)(C + 3 * j0 + 4);   // yb zb
        float qa = fmaf(u0.x, u0.x, fmaf(u0.y, u0.y, u1.x * u1.x));
        float qb = fmaf(u1.y, u1.y, fmaf(u2.x, u2.x, u2.y * u2.y));
        sA[tid] = make_ulonglong2(pack2(u0.x, u1.y), pack2(u0.y, u2.x));
        sB[tid] = make_ulonglong2(pack2(u1.x, u2.y), pack2(qa - THR2, qb - THR2));
        scj[2 * tid]     = asym[a2t[j0]];
        scj[2 * tid + 1] = asym[a2t[j0 + 1]];
    }
    if (tid < NC * NC) scnt[tid] = 0;

    // i-atoms: tid and tid+256 of tile bi
    int i1 = bi * TILE + tid;
    int i2 = i1 + 256;
    float x1 = C[3 * i1], y1 = C[3 * i1 + 1], z1 = C[3 * i1 + 2];
    float x2 = C[3 * i2], y2 = C[3 * i2 + 1], z2 = C[3 * i2 + 2];
    float q1 = fmaf(x1, x1, fmaf(y1, y1, z1 * z1));
    float q2 = fmaf(x2, x2, fmaf(y2, y2, z2 * z2));
    unsigned long long ax1 = pack2(-2.0f * x1, -2.0f * x1);
    unsigned long long ay1 = pack2(-2.0f * y1, -2.0f * y1);
    unsigned long long az1 = pack2(-2.0f * z1, -2.0f * z1);
    unsigned long long Q1  = pack2(q1, q1);
    unsigned long long ax2 = pack2(-2.0f * x2, -2.0f * x2);
    unsigned long long ay2 = pack2(-2.0f * y2, -2.0f * y2);
    unsigned long long az2 = pack2(-2.0f * z2, -2.0f * z2);
    unsigned long long Q2  = pack2(q2, q2);
    int c1 = asym[a2t[i1]] * NC;
    int c2 = asym[a2t[i2]] * NC;

    __syncthreads();

    for (int jj0 = 0; jj0 < TILE / 2; jj0 += UNROLL) {
        unsigned long long acc1 = 0, acc2 = 0;
#pragma unroll
        for (int q = 0; q < UNROLL; ++q) {
            ulonglong2 A = sA[jj0 + q];
            ulonglong2 B = sB[jj0 + q];
            // d = (q_j - thr^2) - 2*dot + q_i   (packed over 2 j-atoms)
            unsigned long long d1 =
                add2(fma2(az1, B.x, fma2(ay1, A.y, fma2(ax1, A.x, B.y))), Q1);
            unsigned long long d2 =
                add2(fma2(az2, B.x, fma2(ay2, A.y, fma2(ax2, A.x, B.y))), Q2);
            acc1 |= d1;              // sticky sign bits at 31 / 63
            acc2 |= d2;
        }
        if (((acc1 | acc2) & SIGNS) != 0ULL) {
            // rare slow path: identical instruction sequence -> identical bits
            for (int q = 0; q < UNROLL; ++q) {
                ulonglong2 A = sA[jj0 + q];
                ulonglong2 B = sB[jj0 + q];
                unsigned long long d1 =
                    add2(fma2(az1, B.x, fma2(ay1, A.y, fma2(ax1, A.x, B.y))), Q1);
                unsigned long long d2 =
                    add2(fma2(az2, B.x, fma2(ay2, A.y, fma2(ax2, A.x, B.y))), Q2);
                unsigned int l1, h1, l2, h2;
                unpack2(d1, l1, h1);
                unpack2(d2, l2, h2);
                int ja = 2 * (jj0 + q), jb = ja + 1;
                if ((int)l1 < 0) atomicAdd(&scnt[c1 + scj[ja]], w);
                if ((int)h1 < 0) atomicAdd(&scnt[c1 + scj[jb]], w);
                if ((int)l2 < 0) atomicAdd(&scnt[c2 + scj[ja]], w);
                if ((int)h2 < 0) atomicAdd(&scnt[c2 + scj[jb]], w);
            }
        }
    }

    __syncthreads();
    if (tid < NC * NC) {
        int v = scnt[tid];
        if (v) atomicAdd(&g_counts[s * NC * NC + tid], v);
    }
}

// ---------------------------------------------------------------------------
// finalize: per-chain atom histogram + thresholds + output, then re-zero
// g_counts so the next graph replay starts clean.
// layout: [ has (S*C*C floats) | details (S*C*C*2 floats, (total, rel)) ]
__global__ void finalize_kernel(const int* __restrict__ asym,
                                const int* __restrict__ a2t,
                                float* __restrict__ out) {
    __shared__ int h[NC];
    int tid = threadIdx.x;
    if (tid < NC) h[tid] = 0;
    __syncthreads();
    for (int i = tid; i < NA; i += 256)
        atomicAdd(&h[asym[a2t[i]]], 1);
    __syncthreads();

    int s = tid / (NC * NC);
    int r = tid % (NC * NC);
    int a = r / NC;
    int b = r % NC;

    int tot_i = 0;
    if (a != b)
        tot_i = (g_counts[s * NC * NC + a * NC + b] +
                 g_counts[s * NC * NC + b * NC + a]) >> 1;   // exact (even)
    float tot = (float)tot_i;
    float mn  = (float)min(h[a], h[b]);
    float rel = tot / mn;
    bool  has = (tot > 100.0f) || (rel > 0.5f);

    out[tid]                        = has ? 1.0f : 0.0f;
    out[NS * NC * NC + 2 * tid]     = tot;
    out[NS * NC * NC + 2 * tid + 1] = rel;

    __syncthreads();          // everyone done reading g_counts
    g_counts[tid] = 0;        // reset for next replay
}

// ---------------------------------------------------------------------------
extern "C" void kernel_launch(void* const* d_in, const int* in_sizes, int n_in,
                              void* d_out, int out_size) {
    const float* coord = (const float*)d_in[0];   // [S, N, 3] f32
    const int*   asym  = (const int*)  d_in[1];   // [N_TOKENS] i32
    const int*   a2t   = (const int*)  d_in[2];   // [N] i32
    float*       out   = (float*)d_out;

    dim3 grid(NTP, NS);
    pair_kernel<<<grid, 256>>>(coord, asym, a2t);
    finalize_kernel<<<1, 256>>>(asym, a2t, out);
}

// round 4
// speedup vs baseline: 3.0423x; 1.4548x over previous
#include <cuda_runtime.h>
#include <cuda_bf16.h>

#define NS     4
#define NA     8192
#define NC     8
#define THR2   1.21f
#define TILE   512
#define NT     (NA / TILE)            // 16
#define NTP    (NT * (NT + 1) / 2)    // 136 tile-pairs

// Zero-initialized at load; finalize re-zeroes after consuming each replay.
__device__ int g_counts[NS * NC * NC];   // weighted ordered-bucket counts
__device__ int g_npc[NC];                // atoms per chain

// ---------------------------------------------------------------------------
__device__ __forceinline__ unsigned long long pack2(float lo, float hi) {
    unsigned long long r;
    asm("mov.b64 %0, {%1, %2};" : "=l"(r) : "f"(lo), "f"(hi));
    return r;
}
__device__ __forceinline__ unsigned long long fma2(unsigned long long a,
                                                   unsigned long long b,
                                                   unsigned long long c) {
    unsigned long long d;
    asm("fma.rn.f32x2 %0, %1, %2, %3;" : "=l"(d) : "l"(a), "l"(b), "l"(c));
    return d;
}
__device__ __forceinline__ unsigned long long add2(unsigned long long a,
                                                   unsigned long long b) {
    unsigned long long d;
    asm("add.rn.f32x2 %0, %1, %2;" : "=l"(d) : "l"(a), "l"(b));
    return d;
}
__device__ __forceinline__ void unpack2(unsigned long long v,
                                        unsigned int& lo, unsigned int& hi) {
    asm("mov.b64 {%0, %1}, %2;" : "=r"(lo), "=r"(hi) : "l"(v));
}

#define SIGNS 0x8000000080000000ULL

// d = q_i - thr^2 + q_j - 2*dot(p_i, p_j), packed over 2 j-atoms.
// smem holds (-2x_j, -2y_j) in A, (-2z_j, q_j) in B; K = q_i - thr^2.
__device__ __forceinline__ unsigned long long pair_d(
    ulonglong2 A, ulonglong2 B,
    unsigned long long X, unsigned long long Y, unsigned long long Z,
    unsigned long long K)
{
    unsigned long long t = fma2(X, A.x, B.y);
    t = fma2(Y, A.y, t);
    t = fma2(Z, B.x, t);
    return add2(t, K);
}

// ---------------------------------------------------------------------------
// 512x512 tiles over the upper triangle of tile space. Off-diag tile-pairs
// count each unordered cross pair once (weight 2); diag tile-pairs count each
// pair twice (weight 1); finalize halves the symmetrized sum. Single-chain
// tiles with ci==cj land entirely in masked diagonal buckets -> skipped.
__global__ __launch_bounds__(256, 4) void pair_kernel(
    const float* __restrict__ coord,
    const int*   __restrict__ asym,
    const int*   __restrict__ a2t)
{
    __shared__ ulonglong2 sA[TILE / 2];   // (-2x, -2y) packed j-pairs
    __shared__ ulonglong2 sB[TILE / 2];   // (-2z, q_j) packed j-pairs
    __shared__ int        scj[TILE];
    __shared__ int        scnt[NC * NC];  // fallback buckets
    __shared__ int        s_tot;          // fast-path block total

    int t = blockIdx.x, bi = 0;
    while (t >= NT - bi) { t -= NT - bi; ++bi; }
    int bj = bi + t;
    int s  = blockIdx.y;
    int w  = (bi == bj) ? 1 : 2;
    int tid = threadIdx.x;

    const float* C = coord + (size_t)s * NA * 3;

    // fill j-tile smem: thread packs atoms (2*tid, 2*tid+1) of tile bj
    int j0 = bj * TILE + 2 * tid;
    float2 u0 = *(const float2*)(C + 3 * j0);       // xa ya
    float2 u1 = *(const float2*)(C + 3 * j0 + 2);   // za xb
    float2 u2 = *(const float2*)(C + 3 * j0 + 4);   // yb zb
    float qa = fmaf(u0.x, u0.x, fmaf(u0.y, u0.y, u1.x * u1.x));
    float qb = fmaf(u1.y, u1.y, fmaf(u2.x, u2.x, u2.y * u2.y));
    sA[tid] = make_ulonglong2(pack2(-2.0f * u0.x, -2.0f * u1.y),
                              pack2(-2.0f * u0.y, -2.0f * u2.x));
    sB[tid] = make_ulonglong2(pack2(-2.0f * u1.x, -2.0f * u2.y),
                              pack2(qa, qb));
    int cj0 = asym[a2t[j0]];
    int cj1 = asym[a2t[j0 + 1]];
    scj[2 * tid]     = cj0;
    scj[2 * tid + 1] = cj1;
    if (tid < NC * NC) scnt[tid] = 0;
    if (tid == 0) s_tot = 0;

    // i-atoms: tid and tid+256 of tile bi
    int i1 = bi * TILE + tid;
    int i2 = i1 + 256;
    float x1 = C[3 * i1], y1 = C[3 * i1 + 1], z1 = C[3 * i1 + 2];
    float x2 = C[3 * i2], y2 = C[3 * i2 + 1], z2 = C[3 * i2 + 2];
    float q1 = fmaf(x1, x1, fmaf(y1, y1, z1 * z1));
    float q2 = fmaf(x2, x2, fmaf(y2, y2, z2 * z2));
    int c1 = asym[a2t[i1]];
    int c2 = asym[a2t[i2]];

    // chain of each tile's first atom (broadcast loads, L1/L2 hits)
    int ciF = asym[a2t[bi * TILE]];
    int cjF = asym[a2t[bj * TILE]];
    int uni = __syncthreads_and(cj0 == cjF && cj1 == cjF &&
                                c1 == ciF && c2 == ciF);

    unsigned long long X1 = pack2(x1, x1), Y1 = pack2(y1, y1);
    unsigned long long Z1 = pack2(z1, z1), K1 = pack2(q1 - THR2, q1 - THR2);
    unsigned long long X2 = pack2(x2, x2), Y2 = pack2(y2, y2);
    unsigned long long Z2 = pack2(z2, z2), K2 = pack2(q2 - THR2, q2 - THR2);

    if (uni) {
        // per-chain atom histogram: each atom lies in exactly one diag tile
        if (s == 0 && bi == bj && tid == 0) atomicAdd(&g_npc[ciF], TILE);
        if (ciF == cjF) return;   // all pairs -> masked diagonal bucket

        int cnt1 = 0, cnt2 = 0;   // accumulate NEGATIVE counts via sign fills
#pragma unroll 8
        for (int jj = 0; jj < TILE / 2; ++jj) {
            ulonglong2 A = sA[jj];
            ulonglong2 B = sB[jj];
            unsigned long long d1 = pair_d(A, B, X1, Y1, Z1, K1);
            unsigned long long d2 = pair_d(A, B, X2, Y2, Z2, K2);
            cnt1 += ((int)(d1 >> 32)) >> 31;
            cnt1 += ((int)d1) >> 31;
            cnt2 += ((int)(d2 >> 32)) >> 31;
            cnt2 += ((int)d2) >> 31;
        }
        int c = cnt1 + cnt2;
        if (c) atomicAdd(&s_tot, c);
        __syncthreads();
        if (tid == 0 && s_tot)
            atomicAdd(&g_counts[s * NC * NC + ciF * NC + cjF], -s_tot * 2);
        return;
    }

    // ---- general fallback: sticky-mask chunks + per-pair bucket atomics ----
    if (s == 0 && bi == bj) {   // histogram for mixed diag tiles
        atomicAdd(&g_npc[c1], 1);
        atomicAdd(&g_npc[c2], 1);
    }
    int b1 = c1 * NC, b2 = c2 * NC;
    for (int jj0 = 0; jj0 < TILE / 2; jj0 += 4) {
        unsigned long long acc = 0;
#pragma unroll
        for (int q = 0; q < 4; ++q) {
            ulonglong2 A = sA[jj0 + q];
            ulonglong2 B = sB[jj0 + q];
            acc |= pair_d(A, B, X1, Y1, Z1, K1);
            acc |= pair_d(A, B, X2, Y2, Z2, K2);
        }
        if ((acc & SIGNS) != 0ULL) {
            for (int q = 0; q < 4; ++q) {
                ulonglong2 A = sA[jj0 + q];
                ulonglong2 B = sB[jj0 + q];
                unsigned long long d1 = pair_d(A, B, X1, Y1, Z1, K1);
                unsigned long long d2 = pair_d(A, B, X2, Y2, Z2, K2);
                unsigned int l1, h1, l2, h2;
                unpack2(d1, l1, h1);
                unpack2(d2, l2, h2);
                int ja = 2 * (jj0 + q), jb = ja + 1;
                if ((int)l1 < 0) atomicAdd(&scnt[b1 + scj[ja]], w);
                if ((int)h1 < 0) atomicAdd(&scnt[b1 + scj[jb]], w);
                if ((int)l2 < 0) atomicAdd(&scnt[b2 + scj[ja]], w);
                if ((int)h2 < 0) atomicAdd(&scnt[b2 + scj[jb]], w);
            }
        }
    }
    __syncthreads();
    if (tid < NC * NC) {
        int v = scnt[tid];
        if (v) atomicAdd(&g_counts[s * NC * NC + tid], v);
    }
}

// ---------------------------------------------------------------------------
// layout: [ has (S*C*C floats) | details (S*C*C*2 floats, (total, rel)) ]
__global__ void finalize_kernel(float* __restrict__ out) {
    int tid = threadIdx.x;          // 0..255 -> (s, a, b)
    int s = tid >> 6;
    int r = tid & 63;
    int a = r >> 3;
    int b = r & 7;

    int tot_i = 0;
    if (a != b)
        tot_i = (g_counts[s * NC * NC + a * NC + b] +
                 g_counts[s * NC * NC + b * NC + a]) >> 1;   // exact (even)
    float tot = (float)tot_i;
    float mn  = (float)min(g_npc[a], g_npc[b]);
    float rel = tot / mn;
    bool  has = (tot > 100.0f) || (rel > 0.5f);

    out[tid]                        = has ? 1.0f : 0.0f;
    out[NS * NC * NC + 2 * tid]     = tot;
    out[NS * NC * NC + 2 * tid + 1] = rel;

    __syncthreads();                // everyone done reading accumulators
    g_counts[tid] = 0;              // reset for next graph replay
    if (tid < NC) g_npc[tid] = 0;
}

// ---------------------------------------------------------------------------
extern "C" void kernel_launch(void* const* d_in, const int* in_sizes, int n_in,
                              void* d_out, int out_size) {
    const float* coord = (const float*)d_in[0];   // [S, N, 3] f32
    const int*   asym  = (const int*)  d_in[1];   // [N_TOKENS] i32
    const int*   a2t   = (const int*)  d_in[2];   // [N] i32
    float*       out   = (float*)d_out;

    dim3 grid(NTP, NS);
    pair_kernel<<<grid, 256>>>(coord, asym, a2t);
    finalize_kernel<<<1, 256>>>(out);
}